// round 8
// baseline (speedup 1.0000x reference)
#include <cuda_runtime.h>
#include <cstdint>

#define NB   2048
#define INS  512
#define SEQL 128
#define NH   12
#define NOUT 3

// scratch (allocation-free contract: __device__ globals)
__device__ float g_pre[(size_t)NB * SEQL * NH];   // [b][s][h]
__device__ float g_hbwd[NB * NH];

__device__ __forceinline__ unsigned long long fma2(unsigned long long a,
                                                   unsigned long long b,
                                                   unsigned long long c) {
    unsigned long long d;
    asm("fma.rn.f32x2 %0, %1, %2, %3;" : "=l"(d) : "l"(a), "l"(b), "l"(c));
    return d;
}
__device__ __forceinline__ unsigned long long pk2(float f) {
    unsigned long long u;
    asm("mov.b64 %0, {%1, %1};" : "=l"(u) : "f"(f));
    return u;
}
__device__ __forceinline__ float ftanh(float x) {
    float e = __expf(2.0f * x);
    return 1.0f - __fdividef(2.0f, e + 1.0f);
}

// ---------------------------------------------------------------------------
// Kernel 1: pre[b,s,h] = sum_i emb[x[b,i], s] * w_ih_f[h,i]
// grid (NB/4, 2); warp per batch; lane owns s0 = 64*y + 2*lane, s1 = s0+1.
// smem = weight pairs only (24 KB) -> __launch_bounds__(128,7) = 28 warps/SM
// (R5 measured occ 29.4% with fma 51%: bubbles need more warps, not MLP).
// Indices via uniform __ldg int4, prefetched 1.5 iterations ahead; e-gather
// 4-i ping-pong LDG.64. 12 fma.rn.f32x2 per i per lane.
// ---------------------------------------------------------------------------
extern "C" __global__ void __launch_bounds__(128, 7)
pre_kernel(const int* __restrict__ x, const float* __restrict__ emb,
           const float* __restrict__ wih) {
    __shared__ float2 w2[INS * 6];   // 24 KB: w2[i*6+k] = (w[2k,i], w[2k+1,i])

    const int tid = threadIdx.x;
    for (int t = tid; t < INS * 6; t += 128) {
        int i = t & (INS - 1);
        int k = t >> 9;              // 0..5
        w2[i * 6 + k] = make_float2(wih[(2 * k) * INS + i],
                                    wih[(2 * k + 1) * INS + i]);
    }
    __syncthreads();

    const int warp = tid >> 5;
    const int lane = tid & 31;
    const int b = blockIdx.x * 4 + warp;
    const int sbase = blockIdx.y * 64 + lane * 2;
    const int4* xrow = (const int4*)(x + (size_t)b * INS);  // 128 int4 groups
    const float* ebase = emb + sbase;

    unsigned long long a0[6], a1[6];   // s0 / s1 accumulators, h-pairs
#pragma unroll
    for (int k = 0; k < 6; k++) { a0[k] = 0ull; a1[k] = 0ull; }

    float2 eA[4], eB[4];
    int4 qB_cur, qA_next, qB_next, qA_nn;

#define LOADE(buf, q)                                                         \
    do {                                                                      \
        buf[0] = *(const float2*)(ebase + (size_t)(q).x * SEQL);              \
        buf[1] = *(const float2*)(ebase + (size_t)(q).y * SEQL);              \
        buf[2] = *(const float2*)(ebase + (size_t)(q).z * SEQL);              \
        buf[3] = *(const float2*)(ebase + (size_t)(q).w * SEQL);              \
    } while (0)

#define COMPUTE4(buf, base_i)                                                 \
    do {                                                                      \
        _Pragma("unroll")                                                     \
        for (int u = 0; u < 4; u++) {                                         \
            unsigned long long p0 = pk2(buf[u].x);                            \
            unsigned long long p1 = pk2(buf[u].y);                            \
            const ulonglong2* wv =                                            \
                (const ulonglong2*)(w2 + (size_t)((base_i) + u) * 6);         \
            ulonglong2 wA = wv[0], wB = wv[1], wC = wv[2];                    \
            a0[0] = fma2(p0, wA.x, a0[0]);                                    \
            a1[0] = fma2(p1, wA.x, a1[0]);                                    \
            a0[1] = fma2(p0, wA.y, a0[1]);                                    \
            a1[1] = fma2(p1, wA.y, a1[1]);                                    \
            a0[2] = fma2(p0, wB.x, a0[2]);                                    \
            a1[2] = fma2(p1, wB.x, a1[2]);                                    \
            a0[3] = fma2(p0, wB.y, a0[3]);                                    \
            a1[3] = fma2(p1, wB.y, a1[3]);                                    \
            a0[4] = fma2(p0, wC.x, a0[4]);                                    \
            a1[4] = fma2(p1, wC.x, a1[4]);                                    \
            a0[5] = fma2(p0, wC.y, a0[5]);                                    \
            a1[5] = fma2(p1, wC.y, a1[5]);                                    \
        }                                                                     \
    } while (0)

    // prologue: q prefetch distance >= 1 iteration ahead of its LOADE
    {
        int4 qA0 = __ldg(xrow + 0);
        qB_cur  = __ldg(xrow + 1);
        qA_next = __ldg(xrow + 2);
        LOADE(eA, qA0);
    }

#pragma unroll 1
    for (int i0 = 0; i0 < INS; i0 += 8) {
        const int j = (i0 >> 2);
        LOADE(eB, qB_cur);                        // q loaded >=1 iter ago
        qB_next = __ldg(xrow + ((j + 3 < 128) ? j + 3 : 0));
        COMPUTE4(eA, i0);
        LOADE(eA, qA_next);                       // q loaded last iter
        qA_nn = __ldg(xrow + ((j + 4 < 128) ? j + 4 : 0));
        COMPUTE4(eB, i0 + 4);
        qB_cur = qB_next;
        qA_next = qA_nn;
    }
#undef LOADE
#undef COMPUTE4

    // [b][s][h]: s0,s1 rows are 24 contiguous floats = 6 x 16B stores
    ulonglong2* d =
        (ulonglong2*)(g_pre + ((size_t)b * SEQL + sbase) * NH);
    ulonglong2 v;
    v.x = a0[0]; v.y = a0[1]; d[0] = v;
    v.x = a0[2]; v.y = a0[3]; d[1] = v;
    v.x = a0[4]; v.y = a0[5]; d[2] = v;
    v.x = a1[0]; v.y = a1[1]; d[3] = v;
    v.x = a1[2]; v.y = a1[3]; d[4] = v;
    v.x = a1[4]; v.y = a1[5]; d[5] = v;
}

// ---------------------------------------------------------------------------
// Kernel 2: h_bwd[b,h] = tanh( sum_i emb[x[b,i],127]*w_ih_r[h,i] + b_ih_r + b_hh_r )
// emb[:,127] staged in smem (2 KB): the gather becomes LDS (~3-way conflicts)
// instead of 250-cyc scattered L2 LDG (this was ~20us in R2-R6).
// Block 128 thr = 4 warps; warp does 2 batches sequentially; grid 256.
// ---------------------------------------------------------------------------
extern "C" __global__ void __launch_bounds__(128)
bwd_kernel(const int* __restrict__ x, const float* __restrict__ emb,
           const float* __restrict__ wir, const float* __restrict__ bir,
           const float* __restrict__ bhr) {
    __shared__ float ws[NH * INS];   // 24 KB
    __shared__ float e127[INS];      // 2 KB
    const int tid = threadIdx.x;
    for (int t = tid; t < NH * INS; t += 128) ws[t] = wir[t];
    for (int t = tid; t < INS; t += 128) e127[t] = emb[(size_t)t * SEQL + (SEQL - 1)];
    __syncthreads();

    const int warp = tid >> 5, lane = tid & 31;

#pragma unroll 1
    for (int bi = 0; bi < 2; bi++) {
        const int b = blockIdx.x * 8 + warp * 2 + bi;

        int idxv[16];
#pragma unroll
        for (int j = 0; j < 16; j++)
            idxv[j] = x[(size_t)b * INS + lane + 32 * j];   // coalesced, 16 in flight
        float ev[16];
#pragma unroll
        for (int j = 0; j < 16; j++) ev[j] = e127[idxv[j]]; // LDS gather

        float p[NH];
#pragma unroll
        for (int h = 0; h < NH; h++) p[h] = 0.f;
#pragma unroll
        for (int j = 0; j < 16; j++) {
            const int i = lane + 32 * j;
#pragma unroll
            for (int h = 0; h < NH; h++) p[h] = fmaf(ev[j], ws[h * INS + i], p[h]);
        }
#pragma unroll
        for (int h = 0; h < NH; h++) {
            float v = p[h];
#pragma unroll
            for (int o = 16; o; o >>= 1) v += __shfl_xor_sync(0xffffffffu, v, o);
            p[h] = v;
        }
        if (lane == 0) {
            float r[NH];
#pragma unroll
            for (int h = 0; h < NH; h++) r[h] = ftanh(p[h] + bir[h] + bhr[h]);
            float4* d = (float4*)(g_hbwd + (size_t)b * NH);
            d[0] = make_float4(r[0], r[1], r[2], r[3]);
            d[1] = make_float4(r[4], r[5], r[6], r[7]);
            d[2] = make_float4(r[8], r[9], r[10], r[11]);
        }
    }
}

// ---------------------------------------------------------------------------
// Kernel 3: forward scan + fused FC epilogue. g_pre is [b][s][h].
// 16 lanes per batch, shfl width 16, depth-3 rolling prefetch with bias
// pre-added off the critical chain. grid 256 (grid-64 regressed in R5-bench).
// ---------------------------------------------------------------------------
extern "C" __global__ void __launch_bounds__(128)
scan_kernel(const float* __restrict__ whh, const float* __restrict__ bih,
            const float* __restrict__ bhh, const float* __restrict__ fcw,
            const float* __restrict__ fcb, float* __restrict__ out) {
    const int tid = threadIdx.x;
    const int b = blockIdx.x * 8 + (tid >> 4);
    const int hl = tid & 15;
    const int hc = hl < NH ? hl : 0;

    float wrow[NH];
#pragma unroll
    for (int j = 0; j < NH; j++) wrow[j] = whh[hc * NH + j];
    const float bias = bih[hc] + bhh[hc];

    const float* ps = g_pre + (size_t)b * SEQL * NH + hc;
    float h = 0.f;
    float p0 = ps[0] + bias, p1 = ps[NH] + bias, p2 = ps[2 * NH] + bias;

    for (int s = 0; s < SEQL; s++) {
        float pb = p0;
        p0 = p1; p1 = p2;
        int sl = (s + 3 < SEQL) ? (s + 3) : 0;
        p2 = ps[(size_t)sl * NH] + bias;

        float v[NH];
#pragma unroll
        for (int j = 0; j < NH; j++) v[j] = __shfl_sync(0xffffffffu, h, j, 16);
        float t0 = fmaf(v[0], wrow[0], pb);
        float t1 = v[1] * wrow[1];
        float t2 = v[2] * wrow[2];
#pragma unroll
        for (int j = 3; j < NH; j += 3) {
            t0 = fmaf(v[j    ], wrow[j    ], t0);
            t1 = fmaf(v[j + 1], wrow[j + 1], t1);
            t2 = fmaf(v[j + 2], wrow[j + 2], t2);
        }
        h = ftanh(t0 + t1 + t2);
    }

    float v[NH];
#pragma unroll
    for (int j = 0; j < NH; j++) v[j] = __shfl_sync(0xffffffffu, h, j, 16);
    if (hl < NOUT) {
        float o = fcb[hl];
        const float* hb = g_hbwd + (size_t)b * NH;
#pragma unroll
        for (int j = 0; j < NH; j++) o = fmaf(v[j], fcw[hl * 2 * NH + j], o);
#pragma unroll
        for (int j = 0; j < NH; j++) o = fmaf(hb[j], fcw[hl * 2 * NH + NH + j], o);
        out[b * NOUT + hl] = o;
    }
}

// ---------------------------------------------------------------------------
extern "C" void kernel_launch(void* const* d_in, const int* in_sizes, int n_in,
                              void* d_out, int out_size) {
    const int*   x      = (const int*)  d_in[0];
    const float* emb    = (const float*)d_in[1];
    const float* w_ih_f = (const float*)d_in[2];
    const float* w_hh_f = (const float*)d_in[3];
    const float* b_ih_f = (const float*)d_in[4];
    const float* b_hh_f = (const float*)d_in[5];
    const float* w_ih_r = (const float*)d_in[6];
    // d_in[7] = w_hh_r (unused: reference consumes only the one-step reverse state)
    const float* b_ih_r = (const float*)d_in[8];
    const float* b_hh_r = (const float*)d_in[9];
    const float* fc_w   = (const float*)d_in[10];
    const float* fc_b   = (const float*)d_in[11];
    float* out = (float*)d_out;

    pre_kernel<<<dim3(NB / 4, 2), 128>>>(x, emb, w_ih_f);
    bwd_kernel<<<NB / 8, 128>>>(x, emb, w_ih_r, b_ih_r, b_hh_r);
    scan_kernel<<<NB / 8, 128>>>(w_hh_f, b_ih_f, b_hh_f, fc_w, fc_b, out);
}

// round 9
// speedup vs baseline: 1.1331x; 1.1331x over previous
#include <cuda_runtime.h>
#include <cstdint>

#define NB   2048
#define INS  512
#define SEQL 128
#define NH   12
#define NOUT 3

// scratch (allocation-free contract: __device__ globals)
__device__ float g_pre0[(size_t)NB * SEQL * NH];   // [b][s][h], K-half 0
__device__ float g_pre1[(size_t)NB * SEQL * NH];   // [b][s][h], K-half 1
__device__ float g_hbwd[NB * NH];

__device__ __forceinline__ unsigned long long fma2(unsigned long long a,
                                                   unsigned long long b,
                                                   unsigned long long c) {
    unsigned long long d;
    asm("fma.rn.f32x2 %0, %1, %2, %3;" : "=l"(d) : "l"(a), "l"(b), "l"(c));
    return d;
}
__device__ __forceinline__ unsigned long long pk2(float f) {
    unsigned long long u;
    asm("mov.b64 %0, {%1, %1};" : "=l"(u) : "f"(f));
    return u;
}
__device__ __forceinline__ float ftanh(float x) {
    float e = __expf(2.0f * x);
    return 1.0f - __fdividef(2.0f, e + 1.0f);
}

// ---------------------------------------------------------------------------
// Kernel 1: pre_y[b,s,h] = sum_{i in K-half y} emb[x[b,i], s] * w_ih_f[h,i]
// grid (NB/4, 2): y = K-half (i in [256y, 256y+256)). Warp per batch; lane
// owns s = 4*lane .. 4*lane+3 (full 128 s per warp -> e is ONE coalesced
// LDG.128 per warp-i = 4 wf; weight LDS 3 wf; 7 wf per 48 fma-cyc, halving
// the wavefront/fma ratio that saturated L1 at 76% in R8). K-split keeps
// grid at 1024 so 5 blocks/SM stay fed (R6's one-warp layout starved at 512).
// ---------------------------------------------------------------------------
extern "C" __global__ void __launch_bounds__(128, 5)
pre_kernel(const int* __restrict__ x, const float* __restrict__ emb,
           const float* __restrict__ wih) {
    __shared__ float2 w2[INS * 6];   // 24 KB: w2[i*6+k] = (w[2k,i], w[2k+1,i])

    const int tid = threadIdx.x;
    for (int t = tid; t < INS * 6; t += 128) {
        int i = t & (INS - 1);
        int k = t >> 9;              // 0..5
        w2[i * 6 + k] = make_float2(wih[(2 * k) * INS + i],
                                    wih[(2 * k + 1) * INS + i]);
    }
    __syncthreads();

    const int warp = tid >> 5;
    const int lane = tid & 31;
    const int b = blockIdx.x * 4 + warp;
    const int y = blockIdx.y;            // K-half
    const int ibase = y * 256;
    // int4 groups for this half: 64 groups of 4 i
    const int4* xg = (const int4*)(x + (size_t)b * INS) + y * 64;
    const float* ebase = emb + 4 * lane; // emb[v*SEQL + 4*lane .. +3]

    unsigned long long aa[4][6];         // [s-slot][h-pair]
#pragma unroll
    for (int sp = 0; sp < 4; sp++)
#pragma unroll
        for (int k = 0; k < 6; k++) aa[sp][k] = 0ull;

    float4 eA[4], eB[4];
    int4 qB_cur, qA_next, qB_next, qA_nn;

#define LOADE(buf, q)                                                         \
    do {                                                                      \
        buf[0] = *(const float4*)(ebase + (size_t)(q).x * SEQL);              \
        buf[1] = *(const float4*)(ebase + (size_t)(q).y * SEQL);              \
        buf[2] = *(const float4*)(ebase + (size_t)(q).z * SEQL);              \
        buf[3] = *(const float4*)(ebase + (size_t)(q).w * SEQL);              \
    } while (0)

#define COMPUTE4(buf, bi)                                                     \
    do {                                                                      \
        _Pragma("unroll")                                                     \
        for (int u = 0; u < 4; u++) {                                         \
            unsigned long long p0 = pk2(buf[u].x);                            \
            unsigned long long p1 = pk2(buf[u].y);                            \
            unsigned long long p2 = pk2(buf[u].z);                            \
            unsigned long long p3 = pk2(buf[u].w);                            \
            const ulonglong2* wv =                                            \
                (const ulonglong2*)(w2 + (size_t)((bi) + u) * 6);             \
            ulonglong2 wA = wv[0], wB = wv[1], wC = wv[2];                    \
            aa[0][0] = fma2(p0, wA.x, aa[0][0]);                              \
            aa[1][0] = fma2(p1, wA.x, aa[1][0]);                              \
            aa[2][0] = fma2(p2, wA.x, aa[2][0]);                              \
            aa[3][0] = fma2(p3, wA.x, aa[3][0]);                              \
            aa[0][1] = fma2(p0, wA.y, aa[0][1]);                              \
            aa[1][1] = fma2(p1, wA.y, aa[1][1]);                              \
            aa[2][1] = fma2(p2, wA.y, aa[2][1]);                              \
            aa[3][1] = fma2(p3, wA.y, aa[3][1]);                              \
            aa[0][2] = fma2(p0, wB.x, aa[0][2]);                              \
            aa[1][2] = fma2(p1, wB.x, aa[1][2]);                              \
            aa[2][2] = fma2(p2, wB.x, aa[2][2]);                              \
            aa[3][2] = fma2(p3, wB.x, aa[3][2]);                              \
            aa[0][3] = fma2(p0, wB.y, aa[0][3]);                              \
            aa[1][3] = fma2(p1, wB.y, aa[1][3]);                              \
            aa[2][3] = fma2(p2, wB.y, aa[2][3]);                              \
            aa[3][3] = fma2(p3, wB.y, aa[3][3]);                              \
            aa[0][4] = fma2(p0, wC.x, aa[0][4]);                              \
            aa[1][4] = fma2(p1, wC.x, aa[1][4]);                              \
            aa[2][4] = fma2(p2, wC.x, aa[2][4]);                              \
            aa[3][4] = fma2(p3, wC.x, aa[3][4]);                              \
            aa[0][5] = fma2(p0, wC.y, aa[0][5]);                              \
            aa[1][5] = fma2(p1, wC.y, aa[1][5]);                              \
            aa[2][5] = fma2(p2, wC.y, aa[2][5]);                              \
            aa[3][5] = fma2(p3, wC.y, aa[3][5]);                              \
        }                                                                     \
    } while (0)

    // prologue: index prefetch distance >= 1 iteration ahead of its LOADE
    {
        int4 qA0 = __ldg(xg + 0);
        qB_cur  = __ldg(xg + 1);
        qA_next = __ldg(xg + 2);
        LOADE(eA, qA0);
    }

#pragma unroll 1
    for (int io = 0; io < 256; io += 8) {
        const int j = io >> 2;                    // group index (even)
        LOADE(eB, qB_cur);
        qB_next = __ldg(xg + ((j + 3 < 64) ? j + 3 : 0));
        COMPUTE4(eA, ibase + io);
        LOADE(eA, qA_next);
        qA_nn = __ldg(xg + ((j + 4 < 64) ? j + 4 : 0));
        COMPUTE4(eB, ibase + io + 4);
        qB_cur = qB_next;
        qA_next = qA_nn;
    }
#undef LOADE
#undef COMPUTE4

    // store: lane owns 4 consecutive s rows = 48 contiguous floats
    float* dstb = (y == 0 ? g_pre0 : g_pre1) +
                  ((size_t)b * SEQL + 4 * lane) * NH;
#pragma unroll
    for (int sp = 0; sp < 4; sp++) {
        ulonglong2* d = (ulonglong2*)(dstb + (size_t)sp * NH);
        ulonglong2 v;
        v.x = aa[sp][0]; v.y = aa[sp][1]; d[0] = v;
        v.x = aa[sp][2]; v.y = aa[sp][3]; d[1] = v;
        v.x = aa[sp][4]; v.y = aa[sp][5]; d[2] = v;
    }
}

// ---------------------------------------------------------------------------
// Kernel 2: h_bwd — warp per batch, 256 thr / 8 warps / grid 256 (R4 form;
// R8's 2-sequential-batch variant halved parallelism and regressed).
// ---------------------------------------------------------------------------
extern "C" __global__ void __launch_bounds__(256)
bwd_kernel(const int* __restrict__ x, const float* __restrict__ emb,
           const float* __restrict__ wir, const float* __restrict__ bir,
           const float* __restrict__ bhr) {
    __shared__ float ws[NH * INS];   // 24 KB
    const int tid = threadIdx.x;
    for (int t = tid; t < NH * INS; t += 256) ws[t] = wir[t];
    __syncthreads();

    const int warp = tid >> 5, lane = tid & 31;
    const int b = blockIdx.x * 8 + warp;

    int idxv[16];
#pragma unroll
    for (int j = 0; j < 16; j++)
        idxv[j] = x[(size_t)b * INS + lane + 32 * j];
    float ev[16];
#pragma unroll
    for (int j = 0; j < 16; j++)
        ev[j] = emb[(size_t)idxv[j] * SEQL + (SEQL - 1)];

    float p[NH];
#pragma unroll
    for (int h = 0; h < NH; h++) p[h] = 0.f;
#pragma unroll
    for (int j = 0; j < 16; j++) {
        const int i = lane + 32 * j;
#pragma unroll
        for (int h = 0; h < NH; h++) p[h] = fmaf(ev[j], ws[h * INS + i], p[h]);
    }
#pragma unroll
    for (int h = 0; h < NH; h++) {
        float v = p[h];
#pragma unroll
        for (int o = 16; o; o >>= 1) v += __shfl_xor_sync(0xffffffffu, v, o);
        p[h] = v;
    }
    if (lane == 0) {
        float r[NH];
#pragma unroll
        for (int h = 0; h < NH; h++) r[h] = ftanh(p[h] + bir[h] + bhr[h]);
        float4* d = (float4*)(g_hbwd + (size_t)b * NH);
        d[0] = make_float4(r[0], r[1], r[2], r[3]);
        d[1] = make_float4(r[4], r[5], r[6], r[7]);
        d[2] = make_float4(r[8], r[9], r[10], r[11]);
    }
}

// ---------------------------------------------------------------------------
// Kernel 3: forward scan + fused FC epilogue. Sums the two K-half pre
// buffers ([b][s][h]); combined value + bias hoisted into the depth-3
// rolling prefetch, off the tanh critical chain. grid 256.
// ---------------------------------------------------------------------------
extern "C" __global__ void __launch_bounds__(128)
scan_kernel(const float* __restrict__ whh, const float* __restrict__ bih,
            const float* __restrict__ bhh, const float* __restrict__ fcw,
            const float* __restrict__ fcb, float* __restrict__ out) {
    const int tid = threadIdx.x;
    const int b = blockIdx.x * 8 + (tid >> 4);
    const int hl = tid & 15;
    const int hc = hl < NH ? hl : 0;

    float wrow[NH];
#pragma unroll
    for (int j = 0; j < NH; j++) wrow[j] = whh[hc * NH + j];
    const float bias = bih[hc] + bhh[hc];

    const float* psA = g_pre0 + (size_t)b * SEQL * NH + hc;
    const float* psB = g_pre1 + (size_t)b * SEQL * NH + hc;

    float h = 0.f;
    float p0 = psA[0]      + psB[0]      + bias;
    float p1 = psA[NH]     + psB[NH]     + bias;
    float p2 = psA[2 * NH] + psB[2 * NH] + bias;

    for (int s = 0; s < SEQL; s++) {
        float pb = p0;
        p0 = p1; p1 = p2;
        int sl = (s + 3 < SEQL) ? (s + 3) : 0;
        p2 = psA[(size_t)sl * NH] + psB[(size_t)sl * NH] + bias;

        float v[NH];
#pragma unroll
        for (int j = 0; j < NH; j++) v[j] = __shfl_sync(0xffffffffu, h, j, 16);
        float t0 = fmaf(v[0], wrow[0], pb);
        float t1 = v[1] * wrow[1];
        float t2 = v[2] * wrow[2];
#pragma unroll
        for (int j = 3; j < NH; j += 3) {
            t0 = fmaf(v[j    ], wrow[j    ], t0);
            t1 = fmaf(v[j + 1], wrow[j + 1], t1);
            t2 = fmaf(v[j + 2], wrow[j + 2], t2);
        }
        h = ftanh(t0 + t1 + t2);
    }

    float v[NH];
#pragma unroll
    for (int j = 0; j < NH; j++) v[j] = __shfl_sync(0xffffffffu, h, j, 16);
    if (hl < NOUT) {
        float o = fcb[hl];
        const float* hb = g_hbwd + (size_t)b * NH;
#pragma unroll
        for (int j = 0; j < NH; j++) o = fmaf(v[j], fcw[hl * 2 * NH + j], o);
#pragma unroll
        for (int j = 0; j < NH; j++) o = fmaf(hb[j], fcw[hl * 2 * NH + NH + j], o);
        out[b * NOUT + hl] = o;
    }
}

// ---------------------------------------------------------------------------
extern "C" void kernel_launch(void* const* d_in, const int* in_sizes, int n_in,
                              void* d_out, int out_size) {
    const int*   x      = (const int*)  d_in[0];
    const float* emb    = (const float*)d_in[1];
    const float* w_ih_f = (const float*)d_in[2];
    const float* w_hh_f = (const float*)d_in[3];
    const float* b_ih_f = (const float*)d_in[4];
    const float* b_hh_f = (const float*)d_in[5];
    const float* w_ih_r = (const float*)d_in[6];
    // d_in[7] = w_hh_r (unused: reference consumes only the one-step reverse state)
    const float* b_ih_r = (const float*)d_in[8];
    const float* b_hh_r = (const float*)d_in[9];
    const float* fc_w   = (const float*)d_in[10];
    const float* fc_b   = (const float*)d_in[11];
    float* out = (float*)d_out;

    pre_kernel<<<dim3(NB / 4, 2), 128>>>(x, emb, w_ih_f);
    bwd_kernel<<<NB / 8, 256>>>(x, emb, w_ih_r, b_ih_r, b_hh_r);
    scan_kernel<<<NB / 8, 128>>>(w_hh_f, b_ih_f, b_hh_f, fc_w, fc_b, out);
}

// round 10
// speedup vs baseline: 1.3286x; 1.1725x over previous
#include <cuda_runtime.h>
#include <cstdint>

#define NB   2048
#define INS  512
#define SEQL 128
#define NH   12
#define NOUT 3

// scratch (allocation-free contract: __device__ globals)
__device__ float g_pre0[(size_t)NB * SEQL * NH];   // [b][s][h], K-half 0
__device__ float g_pre1[(size_t)NB * SEQL * NH];   // [b][s][h], K-half 1

__device__ __forceinline__ unsigned long long fma2(unsigned long long a,
                                                   unsigned long long b,
                                                   unsigned long long c) {
    unsigned long long d;
    asm("fma.rn.f32x2 %0, %1, %2, %3;" : "=l"(d) : "l"(a), "l"(b), "l"(c));
    return d;
}
__device__ __forceinline__ unsigned long long pk2(float f) {
    unsigned long long u;
    asm("mov.b64 %0, {%1, %1};" : "=l"(u) : "f"(f));
    return u;
}
__device__ __forceinline__ float ftanh(float x) {
    float e = __expf(2.0f * x);
    return 1.0f - __fdividef(2.0f, e + 1.0f);
}

// ---------------------------------------------------------------------------
// Kernel 1: pre_y[b,s,h] = sum_{i in K-half y} emb[x[b,i], s] * w_ih_f[h,i]
// grid (NB/4, 2): y = K-half. Warp per batch; lane owns s = 4*lane..4*lane+3.
// Only THIS half's weight pairs staged (12 KB, was 24 staging all K in R9):
// halves staging cost and enlarges the L1D carveout so more of the 256KB emb
// stays L1-resident. 32-bit gather address math (alu was 17%).
// ---------------------------------------------------------------------------
extern "C" __global__ void __launch_bounds__(128, 5)
pre_kernel(const int* __restrict__ x, const float* __restrict__ emb,
           const float* __restrict__ wih) {
    __shared__ float2 w2[256 * 6];   // 12 KB: this K-half only

    const int tid = threadIdx.x;
    const int y = blockIdx.y;            // K-half
    const int ibase = y * 256;

    for (int t = tid; t < 256 * 6; t += 128) {
        int il = t & 255;
        int k = t >> 8;                  // 0..5
        w2[il * 6 + k] = make_float2(wih[(2 * k) * INS + ibase + il],
                                     wih[(2 * k + 1) * INS + ibase + il]);
    }
    __syncthreads();

    const int warp = tid >> 5;
    const int lane = tid & 31;
    const int b = blockIdx.x * 4 + warp;
    const int4* xg = (const int4*)(x + (size_t)b * INS) + y * 64;
    const float* ebase = emb + 4 * lane;

    unsigned long long aa[4][6];         // [s-slot][h-pair]
#pragma unroll
    for (int sp = 0; sp < 4; sp++)
#pragma unroll
        for (int k = 0; k < 6; k++) aa[sp][k] = 0ull;

    float4 eA[4], eB[4];
    int4 qB_cur, qA_next, qB_next, qA_nn;

#define LOADE(buf, q)                                                         \
    do {                                                                      \
        buf[0] = *(const float4*)(ebase + ((unsigned)(q).x << 7));            \
        buf[1] = *(const float4*)(ebase + ((unsigned)(q).y << 7));            \
        buf[2] = *(const float4*)(ebase + ((unsigned)(q).z << 7));            \
        buf[3] = *(const float4*)(ebase + ((unsigned)(q).w << 7));            \
    } while (0)

#define COMPUTE4(buf, bi)                                                     \
    do {                                                                      \
        _Pragma("unroll")                                                     \
        for (int u = 0; u < 4; u++) {                                         \
            unsigned long long p0 = pk2(buf[u].x);                            \
            unsigned long long p1 = pk2(buf[u].y);                            \
            unsigned long long p2 = pk2(buf[u].z);                            \
            unsigned long long p3 = pk2(buf[u].w);                            \
            const ulonglong2* wv =                                            \
                (const ulonglong2*)(w2 + (unsigned)((bi) + u) * 6);           \
            ulonglong2 wA = wv[0], wB = wv[1], wC = wv[2];                    \
            aa[0][0] = fma2(p0, wA.x, aa[0][0]);                              \
            aa[1][0] = fma2(p1, wA.x, aa[1][0]);                              \
            aa[2][0] = fma2(p2, wA.x, aa[2][0]);                              \
            aa[3][0] = fma2(p3, wA.x, aa[3][0]);                              \
            aa[0][1] = fma2(p0, wA.y, aa[0][1]);                              \
            aa[1][1] = fma2(p1, wA.y, aa[1][1]);                              \
            aa[2][1] = fma2(p2, wA.y, aa[2][1]);                              \
            aa[3][1] = fma2(p3, wA.y, aa[3][1]);                              \
            aa[0][2] = fma2(p0, wB.x, aa[0][2]);                              \
            aa[1][2] = fma2(p1, wB.x, aa[1][2]);                              \
            aa[2][2] = fma2(p2, wB.x, aa[2][2]);                              \
            aa[3][2] = fma2(p3, wB.x, aa[3][2]);                              \
            aa[0][3] = fma2(p0, wB.y, aa[0][3]);                              \
            aa[1][3] = fma2(p1, wB.y, aa[1][3]);                              \
            aa[2][3] = fma2(p2, wB.y, aa[2][3]);                              \
            aa[3][3] = fma2(p3, wB.y, aa[3][3]);                              \
            aa[0][4] = fma2(p0, wC.x, aa[0][4]);                              \
            aa[1][4] = fma2(p1, wC.x, aa[1][4]);                              \
            aa[2][4] = fma2(p2, wC.x, aa[2][4]);                              \
            aa[3][4] = fma2(p3, wC.x, aa[3][4]);                              \
            aa[0][5] = fma2(p0, wC.y, aa[0][5]);                              \
            aa[1][5] = fma2(p1, wC.y, aa[1][5]);                              \
            aa[2][5] = fma2(p2, wC.y, aa[2][5]);                              \
            aa[3][5] = fma2(p3, wC.y, aa[3][5]);                              \
        }                                                                     \
    } while (0)

    {
        int4 qA0 = __ldg(xg + 0);
        qB_cur  = __ldg(xg + 1);
        qA_next = __ldg(xg + 2);
        LOADE(eA, qA0);
    }

#pragma unroll 1
    for (int io = 0; io < 256; io += 8) {
        const int j = io >> 2;
        LOADE(eB, qB_cur);
        qB_next = __ldg(xg + ((j + 3 < 64) ? j + 3 : 0));
        COMPUTE4(eA, io);
        LOADE(eA, qA_next);
        qA_nn = __ldg(xg + ((j + 4 < 64) ? j + 4 : 0));
        COMPUTE4(eB, io + 4);
        qB_cur = qB_next;
        qA_next = qA_nn;
    }
#undef LOADE
#undef COMPUTE4

    float* dstb = (y == 0 ? g_pre0 : g_pre1) +
                  ((size_t)b * SEQL + 4 * lane) * NH;
#pragma unroll
    for (int sp = 0; sp < 4; sp++) {
        ulonglong2* d = (ulonglong2*)(dstb + (size_t)sp * NH);
        ulonglong2 v;
        v.x = aa[sp][0]; v.y = aa[sp][1]; d[0] = v;
        v.x = aa[sp][2]; v.y = aa[sp][3]; d[1] = v;
        v.x = aa[sp][4]; v.y = aa[sp][5]; d[2] = v;
    }
}

// ---------------------------------------------------------------------------
// Kernel 2: scan + FUSED h_bwd + FC epilogue. The reverse one-step
// (h_bwd = tanh(emb[x[:, :],127] @ w_ih_r^T + b_ih_r + b_hh_r)) is computed
// in-kernel before the recurrence: scan is latency-bound (~60% idle issue
// slots), so the extra ~830 issues/lane ride in the bubbles and one whole
// kernel launch + staging pass disappears.
// 16 lanes per batch; lane l covers i = l+16k (32 i's, all 12 h), then a
// width-16 butterfly reduce; hb stays in-register for the FC tail.
// ---------------------------------------------------------------------------
extern "C" __global__ void __launch_bounds__(128)
scan_kernel(const int* __restrict__ x, const float* __restrict__ emb,
            const float* __restrict__ wir, const float* __restrict__ bir,
            const float* __restrict__ bhr,
            const float* __restrict__ whh, const float* __restrict__ bih,
            const float* __restrict__ bhh, const float* __restrict__ fcw,
            const float* __restrict__ fcb, float* __restrict__ out) {
    __shared__ float ws[NH * INS];   // 24 KB  w_ih_r [h][i]
    __shared__ float e127[INS];      // 2 KB   emb[:,127]

    const int tid = threadIdx.x;
    for (int t = tid; t < NH * INS; t += 128) ws[t] = wir[t];
    for (int t = tid; t < INS; t += 128)
        e127[t] = emb[(size_t)t * SEQL + (SEQL - 1)];
    __syncthreads();

    const int b = blockIdx.x * 8 + (tid >> 4);
    const int hl = tid & 15;
    const int hc = hl < NH ? hl : 0;
    const int* xrow = x + (size_t)b * INS;

    // ---- fused h_bwd accumulation ----
    float acc[NH];
#pragma unroll
    for (int h = 0; h < NH; h++) acc[h] = 0.f;
#pragma unroll 1
    for (int k = 0; k < 32; k += 8) {
        int idv[8];
#pragma unroll
        for (int j = 0; j < 8; j++) idv[j] = xrow[hl + 16 * (k + j)];
#pragma unroll
        for (int j = 0; j < 8; j++) {
            float e = e127[idv[j]];
            const int i = hl + 16 * (k + j);
#pragma unroll
            for (int h = 0; h < NH; h++)
                acc[h] = fmaf(e, ws[h * INS + i], acc[h]);
        }
    }
    float hb;   // this lane's h_bwd[b, hl]
    {
        float mine = 0.f;
#pragma unroll
        for (int h = 0; h < NH; h++) {
            float v = acc[h];
#pragma unroll
            for (int o = 8; o; o >>= 1) v += __shfl_xor_sync(0xffffffffu, v, o, 16);
            if (h == hl) mine = v;
        }
        hb = ftanh(mine + bir[hc] + bhr[hc]);
    }

    // ---- forward recurrence ----
    float wrow[NH];
#pragma unroll
    for (int j = 0; j < NH; j++) wrow[j] = whh[hc * NH + j];
    const float bias = bih[hc] + bhh[hc];

    const float* psA = g_pre0 + (size_t)b * SEQL * NH + hc;
    const float* psB = g_pre1 + (size_t)b * SEQL * NH + hc;

    float h = 0.f;
    float p0 = psA[0]      + psB[0]      + bias;
    float p1 = psA[NH]     + psB[NH]     + bias;
    float p2 = psA[2 * NH] + psB[2 * NH] + bias;

    for (int s = 0; s < SEQL; s++) {
        float pb = p0;
        p0 = p1; p1 = p2;
        int sl = (s + 3 < SEQL) ? (s + 3) : 0;
        p2 = psA[(size_t)sl * NH] + psB[(size_t)sl * NH] + bias;

        float v[NH];
#pragma unroll
        for (int j = 0; j < NH; j++) v[j] = __shfl_sync(0xffffffffu, h, j, 16);
        float t0 = fmaf(v[0], wrow[0], pb);
        float t1 = v[1] * wrow[1];
        float t2 = v[2] * wrow[2];
#pragma unroll
        for (int j = 3; j < NH; j += 3) {
            t0 = fmaf(v[j    ], wrow[j    ], t0);
            t1 = fmaf(v[j + 1], wrow[j + 1], t1);
            t2 = fmaf(v[j + 2], wrow[j + 2], t2);
        }
        h = ftanh(t0 + t1 + t2);
    }

    // ---- FC epilogue ----
    float v[NH], hbv[NH];
#pragma unroll
    for (int j = 0; j < NH; j++) {
        v[j]   = __shfl_sync(0xffffffffu, h,  j, 16);
        hbv[j] = __shfl_sync(0xffffffffu, hb, j, 16);
    }
    if (hl < NOUT) {
        float o = fcb[hl];
#pragma unroll
        for (int j = 0; j < NH; j++) o = fmaf(v[j], fcw[hl * 2 * NH + j], o);
#pragma unroll
        for (int j = 0; j < NH; j++) o = fmaf(hbv[j], fcw[hl * 2 * NH + NH + j], o);
        out[b * NOUT + hl] = o;
    }
}

// ---------------------------------------------------------------------------
extern "C" void kernel_launch(void* const* d_in, const int* in_sizes, int n_in,
                              void* d_out, int out_size) {
    const int*   x      = (const int*)  d_in[0];
    const float* emb    = (const float*)d_in[1];
    const float* w_ih_f = (const float*)d_in[2];
    const float* w_hh_f = (const float*)d_in[3];
    const float* b_ih_f = (const float*)d_in[4];
    const float* b_hh_f = (const float*)d_in[5];
    const float* w_ih_r = (const float*)d_in[6];
    // d_in[7] = w_hh_r (unused: reference consumes only the one-step reverse state)
    const float* b_ih_r = (const float*)d_in[8];
    const float* b_hh_r = (const float*)d_in[9];
    const float* fc_w   = (const float*)d_in[10];
    const float* fc_b   = (const float*)d_in[11];
    float* out = (float*)d_out;

    pre_kernel<<<dim3(NB / 4, 2), 128>>>(x, emb, w_ih_f);
    scan_kernel<<<NB / 8, 128>>>(x, emb, w_ih_r, b_ih_r, b_hh_r,
                                 w_hh_f, b_ih_f, b_hh_f, fc_w, fc_b, out);
}